// round 12
// baseline (speedup 1.0000x reference)
#include <cuda_runtime.h>
#include <cstdint>

// v, out: [8, 4096, 16, 64] f32 ; w: [1, 16, 127]
// offset(b,s,h,e) = ((b*4096 + s)*16 + h)*64 + e ; s = s1*64 + s2
#define SSTR   1024
#define NW     127
#define STAGES 8
#define WSTG   512                 // bytes per warp per stage (16 rows x 32B)
#define STAGEB 2048                // 4 warps * 512B

__device__ __forceinline__ void cpasync16(uint32_t dst, const void* src) {
    asm volatile("cp.async.cg.shared.global [%0], [%1], 16;\n"
                 :: "r"(dst), "l"(src));
}
__device__ __forceinline__ void cpcommit() {
    asm volatile("cp.async.commit_group;\n");
}
__device__ __forceinline__ void cpwait6() {
    asm volatile("cp.async.wait_group 6;\n");
}
__device__ __forceinline__ void fma2(unsigned long long& acc,
                                     unsigned long long a,
                                     unsigned long long b) {
    asm("fma.rn.f32x2 %0, %1, %2, %0;" : "+l"(acc) : "l"(a), "l"(b));
}

// Block = (b, h, e-eighth of 8 floats = 32B = 1 sector). Grid 1024, 128
// threads (4 warps) -> 7 blocks/SM: 98.8% wave efficiency and 28 warps/SM.
// Warp w is a self-contained cp.async pipeline over rows s2 in [16w, 16w+16);
// lane l: rr = l>>1 (row), e4 = l&1 (float4 within the 32B slice).
__global__ __launch_bounds__(128, 7)
void fftbias2d_v10(const float* __restrict__ v,
                   const float* __restrict__ wg,
                   float* __restrict__ out) {
    const int bid = blockIdx.x;
    const int e8  = bid & 7;                 // e-eighth (8 floats)
    const int h   = (bid >> 3) & 15;
    const int b   = bid >> 7;

    const int t  = threadIdx.x;
    const int w  = t >> 5;                   // warp 0..3
    const int l  = t & 31;
    const int rr = l >> 1;                   // row 0..15
    const int e4 = l & 1;                    // float4 within 32B slice

    __shared__ __align__(16) char   ring[STAGES * STAGEB];     // 16 KB
    __shared__ __align__(16) float4 u_part[16][4][2];          // 2 KB
    __shared__ __align__(16) float4 f_sh[64][2];               // 2 KB -> RxV
    __shared__ __align__(16) float4 u_sh[64][2];               // 2 KB -> RxU
    __shared__ float w_ext[128];

    // K[j][s] = w_ext[j + 64 - s], index in [1,127]; w_ext[127] aliases w[0].
    if (t < NW)  w_ext[t]  = wg[h * NW + t];
    if (t == NW) w_ext[NW] = wg[h * NW];

    const float* vb = v + (size_t)b * 4096 * SSTR + h * 64 + e8 * 8;
    const uint32_t stg = (uint32_t)__cvta_generic_to_shared(ring);

    // Warp-private stage fill: lane l loads row 16w+rr, float4 e4.
    #define ISSUE(s1_) {                                                     \
        const uint32_t _d = stg + ((s1_) & 7) * STAGEB + w * WSTG            \
                              + rr * 32 + e4 * 16;                           \
        const float* _s = vb + (size_t)((s1_) * 64 + 16 * w + rr) * SSTR     \
                             + e4 * 4;                                       \
        cpasync16(_d, _s);                                                   \
        cpcommit();                                                          \
    }

    // Deferred u-partial flush: 4-round shuffle over rr, lanes<2 store.
    #define FLUSH_U(p_, ridx_) {                                             \
        (p_).x += __shfl_xor_sync(0xffffffffu, (p_).x, 2);                   \
        (p_).y += __shfl_xor_sync(0xffffffffu, (p_).y, 2);                   \
        (p_).z += __shfl_xor_sync(0xffffffffu, (p_).z, 2);                   \
        (p_).w += __shfl_xor_sync(0xffffffffu, (p_).w, 2);                   \
        (p_).x += __shfl_xor_sync(0xffffffffu, (p_).x, 4);                   \
        (p_).y += __shfl_xor_sync(0xffffffffu, (p_).y, 4);                   \
        (p_).z += __shfl_xor_sync(0xffffffffu, (p_).z, 4);                   \
        (p_).w += __shfl_xor_sync(0xffffffffu, (p_).w, 4);                   \
        (p_).x += __shfl_xor_sync(0xffffffffu, (p_).x, 8);                   \
        (p_).y += __shfl_xor_sync(0xffffffffu, (p_).y, 8);                   \
        (p_).z += __shfl_xor_sync(0xffffffffu, (p_).z, 8);                   \
        (p_).w += __shfl_xor_sync(0xffffffffu, (p_).w, 8);                   \
        (p_).x += __shfl_xor_sync(0xffffffffu, (p_).x, 16);                  \
        (p_).y += __shfl_xor_sync(0xffffffffu, (p_).y, 16);                  \
        (p_).z += __shfl_xor_sync(0xffffffffu, (p_).z, 16);                  \
        (p_).w += __shfl_xor_sync(0xffffffffu, (p_).w, 16);                  \
        if (l < 2) u_part[(ridx_) & 15][w][l] = (p_);                        \
    }

    #pragma unroll
    for (int s1 = 0; s1 < STAGES - 1; ++s1) ISSUE(s1);

    float4 fa   = make_float4(0.f, 0.f, 0.f, 0.f);
    float4 pend = make_float4(0.f, 0.f, 0.f, 0.f);

    for (int grp = 0; grp < 8; ++grp) {
        #pragma unroll
        for (int i = 0; i < 8; ++i) {
            const int s1 = grp * 8 + i;
            cpwait6();                        // this warp's stage s1 resident
            const char* buf = ring + (s1 & 7) * STAGEB + w * WSTG
                                   + rr * 32 + e4 * 16;
            const float4 a = *(const float4*)buf;
            if (s1 + STAGES - 1 < 64) ISSUE(s1 + STAGES - 1) else cpcommit();
            if (i > 0) FLUSH_U(pend, s1 - 1);          // previous stage
            fa.x += a.x; fa.y += a.y; fa.z += a.z; fa.w += a.w;
            pend = a;
        }
        FLUSH_U(pend, grp * 8 + 7);           // peel last stage of the group
        __syncthreads();                      // group's u_part complete
        if (t < 16) {                         // fold 4 warp-partials
            const int s1g = grp * 8 + (t >> 1);
            const int eq  = t & 1;
            float4 a = make_float4(0.f, 0.f, 0.f, 0.f);
            #pragma unroll
            for (int w2 = 0; w2 < 4; ++w2) {
                const float4 p = u_part[s1g & 15][w2][eq];
                a.x += p.x; a.y += p.y; a.z += p.z; a.w += p.w;
            }
            u_sh[s1g][eq] = a;
        }
        // next group writes the other ring parity -> no second barrier
    }
    f_sh[16 * w + rr][e4] = fa;               // f[s2][e4]
    __syncthreads();

    // ---- Phase 2 (packed f32x2): RxV[j] = sum_s K[j,s] f[s]; RxU likewise.
    // Thread t: e4p = t&1, j = t>>1 (0..63).
    {
        const int e4p = t & 1;
        const int j   = t >> 1;
        ulonglong2 rv = {0ull, 0ull};
        ulonglong2 ru = {0ull, 0ull};
        #pragma unroll 4
        for (int s = 0; s < 64; ++s) {
            const ulonglong2 fv = *(const ulonglong2*)&f_sh[s][e4p];
            const ulonglong2 uv = *(const ulonglong2*)&u_sh[s][e4p];
            const float wa = w_ext[j + 64 - s];
            unsigned long long wa2;
            asm("mov.b64 %0, {%1, %1};" : "=l"(wa2) : "r"(__float_as_uint(wa)));
            fma2(rv.x, fv.x, wa2);  fma2(rv.y, fv.y, wa2);
            fma2(ru.x, uv.x, wa2);  fma2(ru.y, uv.y, wa2);
        }
        __syncthreads();                      // all reads done before overwrite
        *(ulonglong2*)&f_sh[j][e4p] = rv;     // f_sh now holds RxV
        *(ulonglong2*)&u_sh[j][e4p] = ru;     // u_sh now holds RxU
    }
    __syncthreads();

    // ---- Phase 3: out[s1*64+s2] = RxV[s2] + RxU[s1]; 32B sector segments.
    {
        const float4 rva = f_sh[16 * w + rr][e4];
        float* ob = out + (size_t)b * 4096 * SSTR + h * 64 + e8 * 8 + e4 * 4
                        + (size_t)(16 * w + rr) * SSTR;
        #pragma unroll 4
        for (int s1 = 0; s1 < 64; ++s1) {
            const float4 ru = u_sh[s1][e4];   // broadcast (2 addrs/warp)
            float4 o;
            o.x = rva.x + ru.x;
            o.y = rva.y + ru.y;
            o.z = rva.z + ru.z;
            o.w = rva.w + ru.w;
            *(float4*)(ob + (size_t)(s1 * 64) * SSTR) = o;
        }
    }
}

extern "C" void kernel_launch(void* const* d_in, const int* in_sizes, int n_in,
                              void* d_out, int out_size) {
    (void)in_sizes; (void)n_in; (void)out_size;
    const float* v = (const float*)d_in[0];
    const float* w = (const float*)d_in[1];
    float* o = (float*)d_out;
    fftbias2d_v10<<<1024, 128>>>(v, w, o);
}

// round 14
// speedup vs baseline: 1.1353x; 1.1353x over previous
#include <cuda_runtime.h>
#include <cstdint>

// v, out: [8, 4096, 16, 64] f32 ; w: [1, 16, 127]
// offset(b,s,h,e) = ((b*4096 + s)*16 + h)*64 + e ; s = s1*64 + s2
#define SSTR   1024
#define NW     127
#define STAGES 8
#define WSTG   512                 // bytes per warp per stage (8 rows x 64B)
#define STAGEB 4096                // 8 warps * 512B

__device__ __forceinline__ void cpasync16(uint32_t dst, const void* src) {
    asm volatile("cp.async.cg.shared.global [%0], [%1], 16;\n"
                 :: "r"(dst), "l"(src));
}
__device__ __forceinline__ void cpcommit() {
    asm volatile("cp.async.commit_group;\n");
}
__device__ __forceinline__ void cpwait6() {
    asm volatile("cp.async.wait_group 6;\n");
}
__device__ __forceinline__ void fma2(unsigned long long& acc,
                                     unsigned long long a,
                                     unsigned long long b) {
    asm("fma.rn.f32x2 %0, %1, %2, %0;" : "+l"(acc) : "l"(a), "l"(b));
}

extern __shared__ char ring[];      // STAGES * STAGEB = 32 KB

// Block = (b, h, e-quarter of 16 floats = 64B). Grid 512, 256 threads (8
// warps) -> 3-4 blocks/SM (24-32 warps) and 98.8% wave efficiency, with 64B
// DRAM segments (2 full sectors). Warp w is a self-contained cp.async
// pipeline over s2 rows [8w, 8w+8); lane l: rw = l>>2, e4 = l&3.
__global__ __launch_bounds__(256)
void fftbias2d_v12(const float* __restrict__ v,
                   const float* __restrict__ wg,
                   float* __restrict__ out) {
    const int bid = blockIdx.x;
    const int eq  = bid & 3;                 // e-quarter (16 floats)
    const int h   = (bid >> 2) & 15;
    const int b   = bid >> 6;

    const int t  = threadIdx.x;
    const int w  = t >> 5;                   // warp 0..7
    const int l  = t & 31;
    const int rw = l >> 2;                   // row 0..7
    const int e4 = l & 3;                    // float4 within 64B slice

    __shared__ __align__(16) float4 u_part[16][8][4];  // [ring][w][e4] 8 KB
    __shared__ __align__(16) float4 f_sh[64][4];       // f[s2][e4] -> RxV 4 KB
    __shared__ __align__(16) float4 u_sh[64][4];       // u[s1][e4] -> RxU 4 KB
    __shared__ float w_ext[128];

    // K[j][s] = w_ext[j + 64 - s], index in [1,127]; w_ext[127] aliases w[0].
    if (t < NW)  w_ext[t]  = wg[h * NW + t];
    if (t == NW) w_ext[NW] = wg[h * NW];

    const float* vb = v + (size_t)b * 4096 * SSTR + h * 64 + eq * 16;
    const uint32_t stg = (uint32_t)__cvta_generic_to_shared(ring);

    // Warp-private stage fill: lane l loads row 8w+rw, float4 e4 (16B).
    // Warp op = 512B contiguous smem (conflict-free), 8 x 64B gmem segments.
    #define ISSUE(s1_) {                                                     \
        const uint32_t _d = stg + ((s1_) & 7) * STAGEB + w * WSTG + l * 16;  \
        const float* _s = vb + (size_t)((s1_) * 64 + 8 * w + rw) * SSTR      \
                             + e4 * 4;                                       \
        cpasync16(_d, _s);                                                   \
        cpcommit();                                                          \
    }

    // Deferred u-partial flush: 3-round shuffle over rw, lanes<4 store.
    #define FLUSH_U(p_, ridx_) {                                             \
        (p_).x += __shfl_xor_sync(0xffffffffu, (p_).x, 4);                   \
        (p_).y += __shfl_xor_sync(0xffffffffu, (p_).y, 4);                   \
        (p_).z += __shfl_xor_sync(0xffffffffu, (p_).z, 4);                   \
        (p_).w += __shfl_xor_sync(0xffffffffu, (p_).w, 4);                   \
        (p_).x += __shfl_xor_sync(0xffffffffu, (p_).x, 8);                   \
        (p_).y += __shfl_xor_sync(0xffffffffu, (p_).y, 8);                   \
        (p_).z += __shfl_xor_sync(0xffffffffu, (p_).z, 8);                   \
        (p_).w += __shfl_xor_sync(0xffffffffu, (p_).w, 8);                   \
        (p_).x += __shfl_xor_sync(0xffffffffu, (p_).x, 16);                  \
        (p_).y += __shfl_xor_sync(0xffffffffu, (p_).y, 16);                  \
        (p_).z += __shfl_xor_sync(0xffffffffu, (p_).z, 16);                  \
        (p_).w += __shfl_xor_sync(0xffffffffu, (p_).w, 16);                  \
        if (l < 4) u_part[(ridx_) & 15][w][l] = (p_);                        \
    }

    #pragma unroll
    for (int s1 = 0; s1 < STAGES - 1; ++s1) ISSUE(s1);

    float4 fa   = make_float4(0.f, 0.f, 0.f, 0.f);
    float4 pend = make_float4(0.f, 0.f, 0.f, 0.f);

    for (int grp = 0; grp < 8; ++grp) {
        #pragma unroll
        for (int i = 0; i < 8; ++i) {
            const int s1 = grp * 8 + i;
            cpwait6();                        // this warp's stage s1 resident
            const char* buf = ring + (s1 & 7) * STAGEB + w * WSTG + l * 16;
            const float4 a = *(const float4*)buf;
            if (s1 + STAGES - 1 < 64) ISSUE(s1 + STAGES - 1) else cpcommit();
            if (i > 0) FLUSH_U(pend, s1 - 1);          // previous stage
            fa.x += a.x; fa.y += a.y; fa.z += a.z; fa.w += a.w;
            pend = a;
        }
        FLUSH_U(pend, grp * 8 + 7);           // peel last stage of the group
        __syncthreads();                      // group's u_part complete
        if (t < 32) {                         // fold 8 warp-partials
            const int s1g = grp * 8 + (t >> 2);
            const int eg  = t & 3;
            float4 a = make_float4(0.f, 0.f, 0.f, 0.f);
            #pragma unroll
            for (int w2 = 0; w2 < 8; ++w2) {
                const float4 p = u_part[s1g & 15][w2][eg];
                a.x += p.x; a.y += p.y; a.z += p.z; a.w += p.w;
            }
            u_sh[s1g][eg] = a;
        }
        // next group writes the other u_part ring parity -> no 2nd barrier
    }
    f_sh[8 * w + rw][e4] = fa;                // f[s2][e4]
    __syncthreads();

    // ---- Phase 2 (packed f32x2): RxV[j] = sum_s K[j,s] f[s]; RxU likewise.
    // Thread t: e4p = t&3, j = t>>2 (0..63).
    {
        const int e4p = t & 3;
        const int j   = t >> 2;
        ulonglong2 rv = {0ull, 0ull};
        ulonglong2 ru = {0ull, 0ull};
        #pragma unroll 4
        for (int s = 0; s < 64; ++s) {
            const ulonglong2 fv = *(const ulonglong2*)&f_sh[s][e4p];
            const ulonglong2 uv = *(const ulonglong2*)&u_sh[s][e4p];
            const float wa = w_ext[j + 64 - s];
            unsigned long long wa2;
            asm("mov.b64 %0, {%1, %1};" : "=l"(wa2) : "r"(__float_as_uint(wa)));
            fma2(rv.x, fv.x, wa2);  fma2(rv.y, fv.y, wa2);
            fma2(ru.x, uv.x, wa2);  fma2(ru.y, uv.y, wa2);
        }
        __syncthreads();                      // all reads done before overwrite
        *(ulonglong2*)&f_sh[j][e4p] = rv;     // f_sh now holds RxV
        *(ulonglong2*)&u_sh[j][e4p] = ru;     // u_sh now holds RxU
    }
    __syncthreads();

    // ---- Phase 3: out[s1*64+s2] = RxV[s2] + RxU[s1]; 8 x 64B per warp op.
    {
        const float4 rva = f_sh[8 * w + rw][e4];
        float* ob = out + (size_t)b * 4096 * SSTR + h * 64 + eq * 16 + e4 * 4
                        + (size_t)(8 * w + rw) * SSTR;
        #pragma unroll 4
        for (int s1 = 0; s1 < 64; ++s1) {
            const float4 ru = u_sh[s1][e4];
            float4 o;
            o.x = rva.x + ru.x;
            o.y = rva.y + ru.y;
            o.z = rva.z + ru.z;
            o.w = rva.w + ru.w;
            *(float4*)(ob + (size_t)(s1 * 64) * SSTR) = o;
        }
    }
}

extern "C" void kernel_launch(void* const* d_in, const int* in_sizes, int n_in,
                              void* d_out, int out_size) {
    (void)in_sizes; (void)n_in; (void)out_size;
    const float* v = (const float*)d_in[0];
    const float* w = (const float*)d_in[1];
    float* o = (float*)d_out;
    // 32 KB dynamic + 16.5 KB static > default 48 KB opt-in: must raise the
    // per-kernel dynamic smem cap (host-side attribute, capture-safe).
    static int attr_set = 0;
    if (!attr_set) {
        cudaFuncSetAttribute(fftbias2d_v12,
                             cudaFuncAttributeMaxDynamicSharedMemorySize,
                             STAGES * STAGEB);
        attr_set = 1;
    }
    fftbias2d_v12<<<512, 256, STAGES * STAGEB>>>(v, w, o);
}

// round 17
// speedup vs baseline: 1.3443x; 1.1841x over previous
#include <cuda_runtime.h>
#include <cstdint>

// v, out: [8, 4096, 16, 64] f32 ; w: [1, 16, 127]
// offset(b,s,h,e) = ((b*4096 + s)*16 + h)*64 + e ; s = s1*64 + s2
#define SSTR   1024
#define NW     127
#define NSLOT  8                  // ring slots
#define STAGEB 8192               // stage = 64 s2-rows x 128B e-half

__device__ __forceinline__ void cpasync16(uint32_t dst, const void* src) {
    asm volatile("cp.async.cg.shared.global [%0], [%1], 16;\n"
                 :: "r"(dst), "l"(src));
}
__device__ __forceinline__ void mbar_init(uint32_t addr, uint32_t cnt) {
    asm volatile("mbarrier.init.shared.b64 [%0], %1;" :: "r"(addr), "r"(cnt)
                 : "memory");
}
__device__ __forceinline__ void mbar_arrive(uint32_t addr) {
    asm volatile("mbarrier.arrive.shared::cta.b64 _, [%0];" :: "r"(addr)
                 : "memory");
}
// .noinc is load-bearing: the expected count is pre-set by mbarrier.init
// (32 lanes); the non-noinc form would inflate the count -> deadlock (R16).
__device__ __forceinline__ void cp_arrive_noinc(uint32_t addr) {
    asm volatile("cp.async.mbarrier.arrive.noinc.shared::cta.b64 [%0];"
                 :: "r"(addr) : "memory");
}
__device__ __forceinline__ void mbar_wait(uint32_t addr, uint32_t parity) {
    asm volatile(
        "{\n\t.reg .pred P;\n\t"
        "W_%=:\n\t"
        "mbarrier.try_wait.parity.acquire.cta.shared::cta.b64 P, [%0], %1;\n\t"
        "@!P bra W_%=;\n\t}"
        :: "r"(addr), "r"(parity) : "memory");
}
__device__ __forceinline__ void fma2(unsigned long long& acc,
                                     unsigned long long a,
                                     unsigned long long b) {
    asm("fma.rn.f32x2 %0, %1, %2, %0;" : "+l"(acc) : "l"(a), "l"(b));
}

extern __shared__ char ring[];      // NSLOT * STAGEB = 64 KB

// Block = (b, h, e-half). Grid 256, 320 threads.
// Warps 8-9: PRODUCERS — fill the ring via cp.async, gated only by empty
// mbarriers (in-flight = ring depth, independent of consumer pace).
// Warps 0-7: CONSUMERS — v8's per-warp f/u reduction from ring slots, full/
// empty mbarrier handshake, named-barrier fold (producers never join).
__global__ __launch_bounds__(320, 2)
void fftbias2d_v14(const float* __restrict__ v,
                   const float* __restrict__ wg,
                   float* __restrict__ out) {
    const int bid = blockIdx.x;
    const int eh  = bid & 1;                 // e-half (32 floats)
    const int h   = (bid >> 1) & 15;
    const int b   = bid >> 5;

    const int t  = threadIdx.x;
    const int w  = t >> 5;                   // warp 0..9
    const int l  = t & 31;
    const int rp = l >> 3;                   // row-in-4 (0..3)
    const int e4 = l & 7;                    // float4 within 128B e-half

    __shared__ __align__(16) float4 u_part[16][8][8];  // 16 KB
    __shared__ __align__(16) float4 f_sh[64][8];       // 8 KB -> RxV
    __shared__ __align__(16) float4 u_sh[64][8];       // 8 KB -> RxU
    __shared__ float w_ext[128];
    __shared__ __align__(8) unsigned long long mbar[2 * NSLOT];

    uint32_t mb;
    {
        uint32_t a;
        asm("{ .reg .u64 tmp; cvta.to.shared.u64 tmp, %1; cvt.u32.u64 %0, tmp; }"
            : "=r"(a) : "l"((const void*)mbar));
        mb = a;
    }
    #define FULLB(s)  (mb + (uint32_t)(s) * 8)
    #define EMPTYB(s) (mb + 64u + (uint32_t)(s) * 8)

    if (t < NW)  w_ext[t]  = wg[h * NW + t];  // K[j][s] = w_ext[j+64-s]
    if (t == NW) w_ext[NW] = wg[h * NW];      // w_ext[127] aliases w[0]
    if (t == 0) {
        #pragma unroll
        for (int s = 0; s < NSLOT; ++s) {
            mbar_init(FULLB(s), 32);          // 32 producer-lane cp-arrives
            mbar_init(EMPTYB(s), 8);          // 8 consumer warps arrive
        }
    }
    __syncthreads();

    const float* vb = v + (size_t)b * 4096 * SSTR + h * 64 + eh * 32;
    const uint32_t stg = (uint32_t)__cvta_generic_to_shared(ring);

    if (w >= 8) {
        // ---------------- producer: p handles s1 with (s1 & 1) == p --------
        const int p = w - 8;
        for (int s1 = p; s1 < 64; s1 += 2) {
            const int slot = s1 & 7;
            if (s1 >= 8) mbar_wait(EMPTYB(slot), ((s1 >> 3) + 1) & 1);
            const uint32_t dbase = stg + slot * STAGEB + l * 16;
            const float* sbase = vb + (size_t)(s1 * 64 + (l >> 3)) * SSTR
                                    + (l & 7) * 4;
            #pragma unroll
            for (int i = 0; i < 16; ++i)      // 4 rows x 128B per op
                cpasync16(dbase + i * 512, sbase + (size_t)(4 * i) * SSTR);
            cp_arrive_noinc(FULLB(slot));     // arrives when all 16 land
        }
    } else {
        // ---------------- consumer: warp w owns s2 rows [8w, 8w+8) --------
        #define FLUSH_U(p_, ridx_) {                                         \
            (p_).x += __shfl_xor_sync(0xffffffffu, (p_).x, 8);               \
            (p_).y += __shfl_xor_sync(0xffffffffu, (p_).y, 8);               \
            (p_).z += __shfl_xor_sync(0xffffffffu, (p_).z, 8);               \
            (p_).w += __shfl_xor_sync(0xffffffffu, (p_).w, 8);               \
            (p_).x += __shfl_xor_sync(0xffffffffu, (p_).x, 16);              \
            (p_).y += __shfl_xor_sync(0xffffffffu, (p_).y, 16);              \
            (p_).z += __shfl_xor_sync(0xffffffffu, (p_).z, 16);              \
            (p_).w += __shfl_xor_sync(0xffffffffu, (p_).w, 16);              \
            if (l < 8) u_part[(ridx_) & 15][w][l] = (p_);                    \
        }
        float4 fa0  = make_float4(0.f, 0.f, 0.f, 0.f);
        float4 fa1  = make_float4(0.f, 0.f, 0.f, 0.f);
        float4 pend = make_float4(0.f, 0.f, 0.f, 0.f);

        for (int grp = 0; grp < 8; ++grp) {
            #pragma unroll
            for (int i = 0; i < 8; ++i) {
                const int s1 = grp * 8 + i;
                const int slot = s1 & 7;
                mbar_wait(FULLB(slot), (s1 >> 3) & 1);
                const char* buf = ring + slot * STAGEB
                                + (8 * w + rp) * 128 + e4 * 16;
                const float4 a0 = *(const float4*)buf;          // row 8w+rp
                const float4 a1 = *(const float4*)(buf + 512);  // row 8w+rp+4
                if (l == 0) mbar_arrive(EMPTYB(slot));          // free slot
                if (i > 0) FLUSH_U(pend, s1 - 1);               // prev stage
                fa0.x += a0.x; fa0.y += a0.y; fa0.z += a0.z; fa0.w += a0.w;
                fa1.x += a1.x; fa1.y += a1.y; fa1.z += a1.z; fa1.w += a1.w;
                pend.x = a0.x + a1.x; pend.y = a0.y + a1.y;
                pend.z = a0.z + a1.z; pend.w = a0.w + a1.w;
            }
            FLUSH_U(pend, grp * 8 + 7);
            asm volatile("bar.sync 1, 256;" ::: "memory");      // consumers only
            if (t < 64) {                     // fold 8 warp-partials
                const int s1g = grp * 8 + (t >> 3);
                const int eq  = t & 7;
                float4 a = make_float4(0.f, 0.f, 0.f, 0.f);
                #pragma unroll
                for (int w2 = 0; w2 < 8; ++w2) {
                    const float4 q = u_part[s1g & 15][w2][eq];
                    a.x += q.x; a.y += q.y; a.z += q.z; a.w += q.w;
                }
                u_sh[s1g][eq] = a;
            }
            // next group writes the other u_part ring parity
        }
        f_sh[8 * w + rp    ][e4] = fa0;
        f_sh[8 * w + rp + 4][e4] = fa1;
    }
    __syncthreads();                          // all 320 threads rejoin

    // ---- Phase 2 (packed f32x2): RxV[j] = sum_s K[j,s] f[s]; RxU likewise.
    {
        ulonglong2 rv0 = {0ull, 0ull}, rv1 = {0ull, 0ull};
        ulonglong2 ru0 = {0ull, 0ull}, ru1 = {0ull, 0ull};
        if (t < 256) {
            #pragma unroll 4
            for (int s = 0; s < 64; ++s) {
                const ulonglong2 fv = *(const ulonglong2*)&f_sh[s][w];
                const ulonglong2 uv = *(const ulonglong2*)&u_sh[s][w];
                const float wa = w_ext[l + 64 - s];
                const float wb = w_ext[l + 96 - s];
                unsigned long long wa2, wb2;
                asm("mov.b64 %0, {%1, %1};" : "=l"(wa2) : "r"(__float_as_uint(wa)));
                asm("mov.b64 %0, {%1, %1};" : "=l"(wb2) : "r"(__float_as_uint(wb)));
                fma2(rv0.x, fv.x, wa2);  fma2(rv0.y, fv.y, wa2);
                fma2(rv1.x, fv.x, wb2);  fma2(rv1.y, fv.y, wb2);
                fma2(ru0.x, uv.x, wa2);  fma2(ru0.y, uv.y, wa2);
                fma2(ru1.x, uv.x, wb2);  fma2(ru1.y, uv.y, wb2);
            }
        }
        __syncthreads();
        if (t < 256) {
            *(ulonglong2*)&f_sh[l     ][w] = rv0;   // f_sh now holds RxV
            *(ulonglong2*)&f_sh[l + 32][w] = rv1;
            *(ulonglong2*)&u_sh[l     ][w] = ru0;   // u_sh now holds RxU
            *(ulonglong2*)&u_sh[l + 32][w] = ru1;
        }
    }
    __syncthreads();

    // ---- Phase 3: out[s1*64+s2] = RxV[s2] + RxU[s1]; 4-full-line STG.128.
    if (t < 256) {
        const int s2a = 4 * w + rp;
        const float4 rva = f_sh[s2a     ][e4];
        const float4 rvb = f_sh[s2a + 32][e4];
        float* ob = out + (size_t)b * 4096 * SSTR + h * 64 + eh * 32 + e4 * 4;
        #pragma unroll 4
        for (int s1 = 0; s1 < 64; ++s1) {
            const float4 ru = u_sh[s1][e4];
            float* r = ob + (size_t)(s1 * 64) * SSTR;
            float4 o0, o1;
            o0.x = rva.x + ru.x; o0.y = rva.y + ru.y;
            o0.z = rva.z + ru.z; o0.w = rva.w + ru.w;
            o1.x = rvb.x + ru.x; o1.y = rvb.y + ru.y;
            o1.z = rvb.z + ru.z; o1.w = rvb.w + ru.w;
            *(float4*)(r + (size_t)s2a * SSTR)        = o0;
            *(float4*)(r + (size_t)(s2a + 32) * SSTR) = o1;
        }
    }
}

extern "C" void kernel_launch(void* const* d_in, const int* in_sizes, int n_in,
                              void* d_out, int out_size) {
    (void)in_sizes; (void)n_in; (void)out_size;
    const float* v = (const float*)d_in[0];
    const float* w = (const float*)d_in[1];
    float* o = (float*)d_out;
    static int attr_set = 0;
    if (!attr_set) {
        cudaFuncSetAttribute(fftbias2d_v14,
                             cudaFuncAttributeMaxDynamicSharedMemorySize,
                             NSLOT * STAGEB);
        attr_set = 1;
    }
    fftbias2d_v14<<<256, 320, NSLOT * STAGEB>>>(v, w, o);
}